// round 7
// baseline (speedup 1.0000x reference)
#include <cuda_runtime.h>

#define NN 100000
#define NE 600000
#define HD 128

// ---------------- scratch (static device memory; no allocs) ----------------
static __device__ float g_x  [NN * HD];
static __device__ float g_y  [NN * HD];
static __device__ float g_agg[NN * HD];
static __device__ float g_p1 [NN * HD];
static __device__ float g_p2 [NN * HD];
static __device__ int   g_deg[NN];
static __device__ int   g_rowptr[NN + 1];
static __device__ int   g_cursor[NN];
static __device__ int   g_col[2 * NE];
static __device__ float g_invdeg[NN];

// ---------------- encoder: x = node_feats(8) @ W_enc + b_enc ----------------
__global__ void k_encoder(const float* __restrict__ ns, const float* __restrict__ pobs,
                          const int* __restrict__ pmask, const float* __restrict__ Wenc,
                          const float* __restrict__ benc, float* __restrict__ x, int n)
{
    __shared__ float sW[8 * HD];
    __shared__ float sb[HD];
    for (int i = threadIdx.x; i < 8 * HD; i += blockDim.x) sW[i] = Wenc[i];
    for (int i = threadIdx.x; i < HD; i += blockDim.x) sb[i] = benc[i];
    __syncthreads();
    int idx = blockIdx.x * blockDim.x + threadIdx.x;
    if (idx >= n * HD) return;
    int node = idx >> 7, h = idx & 127;
    float f0 = ns[node * 6 + 0], f1 = ns[node * 6 + 1], f2 = ns[node * 6 + 2];
    float f3 = ns[node * 6 + 3], f4 = ns[node * 6 + 4], f5 = ns[node * 6 + 5];
    float f6 = pobs[node];
    float f7 = (float)pmask[node];
    float o = sb[h];
    o += f0 * sW[0 * HD + h] + f1 * sW[1 * HD + h] + f2 * sW[2 * HD + h] + f3 * sW[3 * HD + h];
    o += f4 * sW[4 * HD + h] + f5 * sW[5 * HD + h] + f6 * sW[6 * HD + h] + f7 * sW[7 * HD + h];
    x[idx] = o;
}

// ---------------- CSR build ----------------
__global__ void k_zero_deg(int n)
{
    int i = blockIdx.x * blockDim.x + threadIdx.x;
    if (i < n) g_deg[i] = 0;
}

__global__ void k_deg(const int* __restrict__ ei, int ne)
{
    int e = blockIdx.x * blockDim.x + threadIdx.x;
    if (e >= ne) return;
    int s = ei[e], d = ei[ne + e];
    atomicAdd(&g_deg[s], 1);
    atomicAdd(&g_deg[d], 1);
}

// single-block inclusive scan over degrees -> rowptr, cursor, invdeg
__global__ void k_scan(int n)
{
    __shared__ int sh[1024];
    int t = threadIdx.x;
    int carry = 0;
    if (t == 0) g_rowptr[0] = 0;
    for (int base = 0; base < n; base += 1024) {
        int i = base + t;
        int v = (i < n) ? g_deg[i] : 0;
        sh[t] = v;
        __syncthreads();
        for (int off = 1; off < 1024; off <<= 1) {
            int tv = (t >= off) ? sh[t - off] : 0;
            __syncthreads();
            sh[t] += tv;
            __syncthreads();
        }
        if (i < n) {
            int incl = carry + sh[t];
            g_rowptr[i + 1] = incl;
            g_cursor[i] = incl - v;
            g_invdeg[i] = 1.0f / (float)(v > 0 ? v : 1);
        }
        carry += sh[1023];
        __syncthreads();
    }
}

__global__ void k_fill(const int* __restrict__ ei, int ne)
{
    int e = blockIdx.x * blockDim.x + threadIdx.x;
    if (e >= ne) return;
    int s = ei[e], d = ei[ne + e];
    int p = atomicAdd(&g_cursor[d], 1);
    g_col[p] = s;
    int q = atomicAdd(&g_cursor[s], 1);
    g_col[q] = d;
}

// ---------------- mean aggregation: one warp per node, float4/lane ----------------
__global__ void k_agg(const float* __restrict__ x, float* __restrict__ agg, int n)
{
    int w = (blockIdx.x * blockDim.x + threadIdx.x) >> 5;
    int lane = threadIdx.x & 31;
    if (w >= n) return;
    int beg = g_rowptr[w], end = g_rowptr[w + 1];
    float4 acc = make_float4(0.f, 0.f, 0.f, 0.f);
    for (int i = beg; i < end; i++) {
        int nb = g_col[i];
        float4 v = *reinterpret_cast<const float4*>(&x[(size_t)nb * HD + lane * 4]);
        acc.x += v.x; acc.y += v.y; acc.z += v.z; acc.w += v.w;
    }
    float sc = g_invdeg[w];
    acc.x *= sc; acc.y *= sc; acc.z *= sc; acc.w *= sc;
    *reinterpret_cast<float4*>(&agg[(size_t)w * HD + lane * 4]) = acc;
}

// ---------------- GNN layer GEMM: y = op(x@Ws + agg@Wn + b) ----------------
// 256 threads, 64 rows/block, 4x8 register tile, A-chunk transposed in smem,
// W streamed via LDG (L1-resident, 64KB each).
__global__ void k_layer(const float* __restrict__ x, const float* __restrict__ agg,
                        const float* __restrict__ Ws, const float* __restrict__ Wn,
                        const float* __restrict__ bias, float* __restrict__ y,
                        int n, int do_relu)
{
    __shared__ float sA[64 * 68];
    int tid = threadIdx.x;
    int row0 = blockIdx.x * 64;
    int rg = tid >> 4, cg = tid & 15;
    float acc[4][8];
#pragma unroll
    for (int i = 0; i < 4; i++)
#pragma unroll
        for (int j = 0; j < 8; j++) acc[i][j] = 0.f;

#pragma unroll 1
    for (int ch = 0; ch < 4; ch++) {
        const float* A = (ch < 2) ? x : agg;
        const float* W = (ch < 2) ? Ws : Wn;
        int kb = (ch & 1) * 64;
        __syncthreads();
        for (int idx = tid; idx < 64 * 64; idx += 256) {
            int k = idx & 63, r = idx >> 6;
            int gr = row0 + r;
            sA[k * 68 + r] = (gr < n) ? A[(size_t)gr * HD + kb + k] : 0.0f;
        }
        __syncthreads();
        const float4* W4 = reinterpret_cast<const float4*>(W);
#pragma unroll 4
        for (int k = 0; k < 64; k++) {
            float4 a = *reinterpret_cast<const float4*>(&sA[k * 68 + rg * 4]);
            int wr = (kb + k) * 32 + cg * 2;
            float4 w0 = __ldg(&W4[wr]);
            float4 w1 = __ldg(&W4[wr + 1]);
            float av[4] = {a.x, a.y, a.z, a.w};
            float wv[8] = {w0.x, w0.y, w0.z, w0.w, w1.x, w1.y, w1.z, w1.w};
#pragma unroll
            for (int i = 0; i < 4; i++)
#pragma unroll
                for (int j = 0; j < 8; j++) acc[i][j] += av[i] * wv[j];
        }
    }

    int c0 = cg * 8;
    float bv[8];
#pragma unroll
    for (int j = 0; j < 8; j++) bv[j] = __ldg(&bias[c0 + j]);
#pragma unroll
    for (int i = 0; i < 4; i++) {
        int r = row0 + rg * 4 + i;
        if (r < n) {
            float o[8];
#pragma unroll
            for (int j = 0; j < 8; j++) {
                float v = acc[i][j] + bv[j];
                o[j] = do_relu ? fmaxf(v, 0.f) : v;
            }
            float4* dst = reinterpret_cast<float4*>(&y[(size_t)r * HD + c0]);
            dst[0] = make_float4(o[0], o[1], o[2], o[3]);
            dst[1] = make_float4(o[4], o[5], o[6], o[7]);
        }
    }
}

// ---------------- edge-head precompute: Ao = x@W1[0:128], Bo = x@W1[128:256] ----------------
__global__ void k_prec(const float* __restrict__ x, const float* __restrict__ W1,
                       float* __restrict__ Ao, float* __restrict__ Bo, int n)
{
    __shared__ float sA[64 * 68];
    int tid = threadIdx.x;
    int row0 = blockIdx.x * 64;
    int rg = tid >> 4, cg = tid & 15;
    float acca[4][8], accb[4][8];
#pragma unroll
    for (int i = 0; i < 4; i++)
#pragma unroll
        for (int j = 0; j < 8; j++) { acca[i][j] = 0.f; accb[i][j] = 0.f; }

    const float4* W4 = reinterpret_cast<const float4*>(W1);
#pragma unroll 1
    for (int ch = 0; ch < 2; ch++) {
        int kb = ch * 64;
        __syncthreads();
        for (int idx = tid; idx < 64 * 64; idx += 256) {
            int k = idx & 63, r = idx >> 6;
            int gr = row0 + r;
            sA[k * 68 + r] = (gr < n) ? x[(size_t)gr * HD + kb + k] : 0.0f;
        }
        __syncthreads();
#pragma unroll 2
        for (int k = 0; k < 64; k++) {
            float4 a = *reinterpret_cast<const float4*>(&sA[k * 68 + rg * 4]);
            int rt = (kb + k) * 32 + cg * 2;
            int rb = (128 + kb + k) * 32 + cg * 2;
            float4 w0 = __ldg(&W4[rt]);
            float4 w1 = __ldg(&W4[rt + 1]);
            float4 u0 = __ldg(&W4[rb]);
            float4 u1 = __ldg(&W4[rb + 1]);
            float av[4] = {a.x, a.y, a.z, a.w};
            float wv[8] = {w0.x, w0.y, w0.z, w0.w, w1.x, w1.y, w1.z, w1.w};
            float uv[8] = {u0.x, u0.y, u0.z, u0.w, u1.x, u1.y, u1.z, u1.w};
#pragma unroll
            for (int i = 0; i < 4; i++)
#pragma unroll
                for (int j = 0; j < 8; j++) {
                    acca[i][j] += av[i] * wv[j];
                    accb[i][j] += av[i] * uv[j];
                }
        }
    }
    int c0 = cg * 8;
#pragma unroll
    for (int i = 0; i < 4; i++) {
        int r = row0 + rg * 4 + i;
        if (r < n) {
            float4* da = reinterpret_cast<float4*>(&Ao[(size_t)r * HD + c0]);
            da[0] = make_float4(acca[i][0], acca[i][1], acca[i][2], acca[i][3]);
            da[1] = make_float4(acca[i][4], acca[i][5], acca[i][6], acca[i][7]);
            float4* db = reinterpret_cast<float4*>(&Bo[(size_t)r * HD + c0]);
            db[0] = make_float4(accb[i][0], accb[i][1], accb[i][2], accb[i][3]);
            db[1] = make_float4(accb[i][4], accb[i][5], accb[i][6], accb[i][7]);
        }
    }
}

// ---------------- fused node heads: out = relu(x@W1+b1)@W2 + b2 (two heads) ----------------
__global__ void k_nodehead(const float* __restrict__ x,
                           const float* __restrict__ W1a, const float* __restrict__ b1a,
                           const float* __restrict__ W2a, const float* __restrict__ b2a,
                           const float* __restrict__ W1b, const float* __restrict__ b1b,
                           const float* __restrict__ W2b, const float* __restrict__ b2b,
                           float* __restrict__ outa, float* __restrict__ outb, int n)
{
    __shared__ float sA[64 * 68];
    int tid = threadIdx.x;
    int row0 = blockIdx.x * 64;
    int rg = tid >> 4, cg = tid & 15;
    float acca[4][8], accb[4][8];
#pragma unroll
    for (int i = 0; i < 4; i++)
#pragma unroll
        for (int j = 0; j < 8; j++) { acca[i][j] = 0.f; accb[i][j] = 0.f; }

    const float4* Wa4 = reinterpret_cast<const float4*>(W1a);
    const float4* Wb4 = reinterpret_cast<const float4*>(W1b);
#pragma unroll 1
    for (int ch = 0; ch < 2; ch++) {
        int kb = ch * 64;
        __syncthreads();
        for (int idx = tid; idx < 64 * 64; idx += 256) {
            int k = idx & 63, r = idx >> 6;
            int gr = row0 + r;
            sA[k * 68 + r] = (gr < n) ? x[(size_t)gr * HD + kb + k] : 0.0f;
        }
        __syncthreads();
#pragma unroll 2
        for (int k = 0; k < 64; k++) {
            float4 a = *reinterpret_cast<const float4*>(&sA[k * 68 + rg * 4]);
            int wr = (kb + k) * 32 + cg * 2;
            float4 w0 = __ldg(&Wa4[wr]);
            float4 w1 = __ldg(&Wa4[wr + 1]);
            float4 u0 = __ldg(&Wb4[wr]);
            float4 u1 = __ldg(&Wb4[wr + 1]);
            float av[4] = {a.x, a.y, a.z, a.w};
            float wv[8] = {w0.x, w0.y, w0.z, w0.w, w1.x, w1.y, w1.z, w1.w};
            float uv[8] = {u0.x, u0.y, u0.z, u0.w, u1.x, u1.y, u1.z, u1.w};
#pragma unroll
            for (int i = 0; i < 4; i++)
#pragma unroll
                for (int j = 0; j < 8; j++) {
                    acca[i][j] += av[i] * wv[j];
                    accb[i][j] += av[i] * uv[j];
                }
        }
    }
    // epilogue: bias + relu + dot(W2), block reduction over 16 col groups
    __syncthreads();
    float* sra = sA;
    float* srb = sA + 1024;
    int c0 = cg * 8;
    float b1av[8], b1bv[8], w2av[8], w2bv[8];
#pragma unroll
    for (int j = 0; j < 8; j++) {
        b1av[j] = __ldg(&b1a[c0 + j]); w2av[j] = __ldg(&W2a[c0 + j]);
        b1bv[j] = __ldg(&b1b[c0 + j]); w2bv[j] = __ldg(&W2b[c0 + j]);
    }
#pragma unroll
    for (int i = 0; i < 4; i++) {
        float pa = 0.f, pb = 0.f;
#pragma unroll
        for (int j = 0; j < 8; j++) {
            float h1 = fmaxf(acca[i][j] + b1av[j], 0.f);
            pa += h1 * w2av[j];
            float h2 = fmaxf(accb[i][j] + b1bv[j], 0.f);
            pb += h2 * w2bv[j];
        }
        int r = rg * 4 + i;
        sra[r * 16 + cg] = pa;
        srb[r * 16 + cg] = pb;
    }
    __syncthreads();
    if (tid < 64) {
        int grow = row0 + tid;
        if (grow < n) {
            float sa = 0.f, sb = 0.f;
#pragma unroll
            for (int c = 0; c < 16; c++) { sa += sra[tid * 16 + c]; sb += srb[tid * 16 + c]; }
            outa[grow] = sa + __ldg(&b2a[0]);
            outb[grow] = sb + __ldg(&b2b[0]);
        }
    }
}

// ---------------- edge heads: one warp per edge, gather A[src]+B[dst]+static part ----------------
__global__ void k_edge(const int* __restrict__ ei,
                       const float* __restrict__ estat, const float* __restrict__ qobs,
                       const int* __restrict__ qmask,
                       const float* __restrict__ erW1, const float* __restrict__ erb1,
                       const float* __restrict__ erW2, const float* __restrict__ erb2,
                       const float* __restrict__ eaW1, const float* __restrict__ eab1,
                       const float* __restrict__ eaW2, const float* __restrict__ eab2,
                       float* __restrict__ qhat, float* __restrict__ elog, int ne)
{
    __shared__ float sE[2][8 * HD];  // per head: rows 0-5 = W1[256+r], 6 = b1, 7 = W2
    int tid = threadIdx.x;
    for (int idx = tid; idx < 2 * 8 * HD; idx += blockDim.x) {
        int h = idx / (8 * HD);
        int rem = idx - h * 8 * HD;
        int r = rem >> 7, c = rem & 127;
        const float* W1 = h ? eaW1 : erW1;
        const float* b1 = h ? eab1 : erb1;
        const float* W2 = h ? eaW2 : erW2;
        float v;
        if (r < 6) v = W1[(256 + r) * HD + c];
        else if (r == 6) v = b1[c];
        else v = W2[c];
        sE[h][rem] = v;
    }
    __syncthreads();

    int w = (blockIdx.x * blockDim.x + tid) >> 5;
    int lane = tid & 31;
    if (w >= ne) return;
    int s = ei[w], d = ei[ne + w];
    float e0 = estat[w * 4 + 0], e1 = estat[w * 4 + 1];
    float e2 = estat[w * 4 + 2], e3 = estat[w * 4 + 3];
    float qo = qobs[w], qm = (float)qmask[w];
    int c = lane * 4;

    // head er: A in g_x, B in g_agg
    {
        const float* S = sE[0];
        float4 a = *reinterpret_cast<const float4*>(&g_x[(size_t)s * HD + c]);
        float4 b = *reinterpret_cast<const float4*>(&g_agg[(size_t)d * HD + c]);
        float av[4] = {a.x, a.y, a.z, a.w};
        float bv[4] = {b.x, b.y, b.z, b.w};
        float acc = 0.f;
#pragma unroll
        for (int t = 0; t < 4; t++) {
            int cc = c + t;
            float hv = av[t] + bv[t] + e0 * S[cc] + e1 * S[HD + cc] + e2 * S[2 * HD + cc]
                     + e3 * S[3 * HD + cc] + qo * S[4 * HD + cc] + qm * S[5 * HD + cc]
                     + S[6 * HD + cc];
            hv = fmaxf(hv, 0.f);
            acc += hv * S[7 * HD + cc];
        }
#pragma unroll
        for (int off = 16; off; off >>= 1) acc += __shfl_xor_sync(0xffffffffu, acc, off);
        if (lane == 0) qhat[w] = acc + __ldg(&erb2[0]);
    }
    // head ea: A in g_p1, B in g_p2
    {
        const float* S = sE[1];
        float4 a = *reinterpret_cast<const float4*>(&g_p1[(size_t)s * HD + c]);
        float4 b = *reinterpret_cast<const float4*>(&g_p2[(size_t)d * HD + c]);
        float av[4] = {a.x, a.y, a.z, a.w};
        float bv[4] = {b.x, b.y, b.z, b.w};
        float acc = 0.f;
#pragma unroll
        for (int t = 0; t < 4; t++) {
            int cc = c + t;
            float hv = av[t] + bv[t] + e0 * S[cc] + e1 * S[HD + cc] + e2 * S[2 * HD + cc]
                     + e3 * S[3 * HD + cc] + qo * S[4 * HD + cc] + qm * S[5 * HD + cc]
                     + S[6 * HD + cc];
            hv = fmaxf(hv, 0.f);
            acc += hv * S[7 * HD + cc];
        }
#pragma unroll
        for (int off = 16; off; off >>= 1) acc += __shfl_xor_sync(0xffffffffu, acc, off);
        if (lane == 0) elog[w] = acc + __ldg(&eab2[0]);
    }
}

// ---------------- launch ----------------
extern "C" void kernel_launch(void* const* d_in, const int* in_sizes, int n_in,
                              void* d_out, int out_size)
{
    const int*   ei           = (const int*)d_in[0];   // edge_index is int32 (jax x64 disabled)
    const float* node_static  = (const float*)d_in[1];
    const float* edge_static  = (const float*)d_in[2];
    const float* p_obs        = (const float*)d_in[3];
    const float* q_obs        = (const float*)d_in[4];
    const int*   p_mask       = (const int*)d_in[5];
    const int*   q_mask       = (const int*)d_in[6];
    const float* W_enc        = (const float*)d_in[7];
    const float* b_enc        = (const float*)d_in[8];
    const float* W_self       = (const float*)d_in[9];
    const float* W_neigh      = (const float*)d_in[10];
    const float* b_gnn        = (const float*)d_in[11];
    const float* nrW1 = (const float*)d_in[12]; const float* nrb1 = (const float*)d_in[13];
    const float* nrW2 = (const float*)d_in[14]; const float* nrb2 = (const float*)d_in[15];
    const float* naW1 = (const float*)d_in[16]; const float* nab1 = (const float*)d_in[17];
    const float* naW2 = (const float*)d_in[18]; const float* nab2 = (const float*)d_in[19];
    const float* erW1 = (const float*)d_in[20]; const float* erb1 = (const float*)d_in[21];
    const float* erW2 = (const float*)d_in[22]; const float* erb2 = (const float*)d_in[23];
    const float* eaW1 = (const float*)d_in[24]; const float* eab1 = (const float*)d_in[25];
    const float* eaW2 = (const float*)d_in[26]; const float* eab2 = (const float*)d_in[27];

    int n  = in_sizes[3];  // N (p_obs)
    int ne = in_sizes[4];  // E (q_obs)

    float* out   = (float*)d_out;
    float* p_hat = out;
    float* q_hat = out + n;
    float* nlog  = out + n + ne;
    float* elog  = out + 2 * n + ne;

    float *gx, *gy, *gagg, *gp1, *gp2;
    cudaGetSymbolAddress((void**)&gx,   g_x);
    cudaGetSymbolAddress((void**)&gy,   g_y);
    cudaGetSymbolAddress((void**)&gagg, g_agg);
    cudaGetSymbolAddress((void**)&gp1,  g_p1);
    cudaGetSymbolAddress((void**)&gp2,  g_p2);

    k_encoder<<<(n * HD + 255) / 256, 256>>>(node_static, p_obs, p_mask, W_enc, b_enc, gx, n);
    k_zero_deg<<<(n + 255) / 256, 256>>>(n);
    k_deg<<<(ne + 255) / 256, 256>>>(ei, ne);
    k_scan<<<1, 1024>>>(n);
    k_fill<<<(ne + 255) / 256, 256>>>(ei, ne);

    const float* xin = gx;
    float* xout = gy;
    for (int l = 0; l < 3; l++) {
        k_agg<<<(n * 32 + 255) / 256, 256>>>(xin, gagg, n);
        k_layer<<<(n + 63) / 64, 256>>>(xin, gagg, W_self + l * HD * HD, W_neigh + l * HD * HD,
                                        b_gnn + l * HD, xout, n, (l < 2) ? 1 : 0);
        const float* t = xin;
        xin = xout;
        xout = (float*)t;
    }
    const float* xf = xin;  // final node embeddings (g_y)

    k_nodehead<<<(n + 63) / 64, 256>>>(xf, nrW1, nrb1, nrW2, nrb2,
                                       naW1, nab1, naW2, nab2, p_hat, nlog, n);
    // edge-head per-node precompute: er -> (g_x, g_agg), ea -> (g_p1, g_p2)
    k_prec<<<(n + 63) / 64, 256>>>(xf, erW1, gx, gagg, n);
    k_prec<<<(n + 63) / 64, 256>>>(xf, eaW1, gp1, gp2, n);

    k_edge<<<(ne * 32 + 255) / 256, 256>>>(ei, edge_static, q_obs, q_mask,
                                           erW1, erb1, erW2, erb2,
                                           eaW1, eab1, eaW2, eab2,
                                           q_hat, elog, ne);
}

// round 8
// speedup vs baseline: 2.0466x; 2.0466x over previous
#include <cuda_runtime.h>
#include <cstdint>

#define NN 100000
#define NE 600000
#define HD 128

// ---------------- scratch (static device memory; no allocs) ----------------
static __device__ float g_x  [NN * HD];
static __device__ float g_y  [NN * HD];
static __device__ float g_agg[NN * HD];
static __device__ float g_p1 [NN * HD];
static __device__ float g_p2 [NN * HD];
static __device__ int   g_deg[NN];
static __device__ int   g_rowptr[NN + 1];
static __device__ int   g_cursor[NN];
static __device__ int   g_col[2 * NE];
static __device__ float g_invdeg[NN];
static __device__ int   g_tmp[NN];
static __device__ int   g_bsum[128];

// ---------------- encoder: x = node_feats(8) @ W_enc + b_enc ----------------
__global__ void k_encoder(const float* __restrict__ ns, const float* __restrict__ pobs,
                          const int* __restrict__ pmask, const float* __restrict__ Wenc,
                          const float* __restrict__ benc, float* __restrict__ x, int n)
{
    __shared__ float sW[8 * HD];
    __shared__ float sb[HD];
    for (int i = threadIdx.x; i < 8 * HD; i += blockDim.x) sW[i] = Wenc[i];
    for (int i = threadIdx.x; i < HD; i += blockDim.x) sb[i] = benc[i];
    __syncthreads();
    int idx = blockIdx.x * blockDim.x + threadIdx.x;
    if (idx >= n * HD) return;
    int node = idx >> 7, h = idx & 127;
    float f0 = ns[node * 6 + 0], f1 = ns[node * 6 + 1], f2 = ns[node * 6 + 2];
    float f3 = ns[node * 6 + 3], f4 = ns[node * 6 + 4], f5 = ns[node * 6 + 5];
    float f6 = pobs[node];
    float f7 = (float)pmask[node];
    float o = sb[h];
    o += f0 * sW[0 * HD + h] + f1 * sW[1 * HD + h] + f2 * sW[2 * HD + h] + f3 * sW[3 * HD + h];
    o += f4 * sW[4 * HD + h] + f5 * sW[5 * HD + h] + f6 * sW[6 * HD + h] + f7 * sW[7 * HD + h];
    x[idx] = o;
}

// ---------------- CSR build ----------------
__global__ void k_zero_deg(int n)
{
    int i = blockIdx.x * blockDim.x + threadIdx.x;
    if (i < n) g_deg[i] = 0;
}

__global__ void k_deg(const int* __restrict__ ei, int ne)
{
    int e = blockIdx.x * blockDim.x + threadIdx.x;
    if (e >= ne) return;
    int s = ei[e], d = ei[ne + e];
    atomicAdd(&g_deg[s], 1);
    atomicAdd(&g_deg[d], 1);
}

// multi-block scan: local inclusive scan per 1024-block
__global__ void k_scan_local(int n)
{
    __shared__ int sh[1024];
    int t = threadIdx.x;
    int i = blockIdx.x * 1024 + t;
    int v = (i < n) ? g_deg[i] : 0;
    sh[t] = v;
    __syncthreads();
    for (int off = 1; off < 1024; off <<= 1) {
        int tv = (t >= off) ? sh[t - off] : 0;
        __syncthreads();
        sh[t] += tv;
        __syncthreads();
    }
    if (i < n) g_tmp[i] = sh[t];
    if (t == 1023) g_bsum[blockIdx.x] = sh[1023];
}

__global__ void k_scan_bsum(int nb)
{
    if (threadIdx.x == 0) {
        int acc = 0;
        for (int b = 0; b < nb; b++) { int tv = g_bsum[b]; g_bsum[b] = acc; acc += tv; }
    }
}

__global__ void k_scan_final(int n)
{
    int i = blockIdx.x * blockDim.x + threadIdx.x;
    if (i >= n) return;
    int incl = g_tmp[i] + g_bsum[i >> 10];
    g_rowptr[i + 1] = incl;
    int d = g_deg[i];
    g_cursor[i] = incl - d;
    g_invdeg[i] = 1.0f / (float)(d > 0 ? d : 1);
    if (i == 0) g_rowptr[0] = 0;
}

__global__ void k_fill(const int* __restrict__ ei, int ne)
{
    int e = blockIdx.x * blockDim.x + threadIdx.x;
    if (e >= ne) return;
    int s = ei[e], d = ei[ne + e];
    int p = atomicAdd(&g_cursor[d], 1);
    g_col[p] = s;
    int q = atomicAdd(&g_cursor[s], 1);
    g_col[q] = d;
}

// ---------------- mean aggregation: one warp per node, float4/lane ----------------
__global__ void k_agg(const float* __restrict__ x, float* __restrict__ agg, int n)
{
    int w = (blockIdx.x * blockDim.x + threadIdx.x) >> 5;
    int lane = threadIdx.x & 31;
    if (w >= n) return;
    int beg = g_rowptr[w], end = g_rowptr[w + 1];
    float4 acc = make_float4(0.f, 0.f, 0.f, 0.f);
    for (int i = beg; i < end; i++) {
        int nb = g_col[i];
        float4 v = *reinterpret_cast<const float4*>(&x[(size_t)nb * HD + lane * 4]);
        acc.x += v.x; acc.y += v.y; acc.z += v.z; acc.w += v.w;
    }
    float sc = g_invdeg[w];
    acc.x *= sc; acc.y *= sc; acc.z *= sc; acc.w *= sc;
    *reinterpret_cast<float4*>(&agg[(size_t)w * HD + lane * 4]) = acc;
}

// ---------------- tf32 tensor-core GEMM: C = op(A@W0 [+ A2@W1] + bias) ----------------
__device__ __forceinline__ uint32_t f2tf(float f)
{
    uint32_t r;
    asm("cvt.rna.tf32.f32 %0, %1;" : "=r"(r) : "f"(f));
    return r;
}

#define MMA8(c, a0, a1, a2, a3, b0, b1)                                     \
    asm volatile("mma.sync.aligned.m16n8k8.row.col.f32.tf32.tf32.f32 "      \
                 "{%0,%1,%2,%3},{%4,%5,%6,%7},{%8,%9},{%0,%1,%2,%3};"       \
                 : "+f"((c)[0]), "+f"((c)[1]), "+f"((c)[2]), "+f"((c)[3])   \
                 : "r"(a0), "r"(a1), "r"(a2), "r"(a3), "r"(b0), "r"(b1))

// Block: 256 threads (8 warps), tile 64 rows x 128 cols, K = 128.
// Warp w owns cols [w*16, w*16+16) = 2 n-tiles; loops over 4 slabs of 16 rows.
// W packed in smem in mma-fragment order -> conflict-free LDS.64.
// A staged in smem, stride 132 -> A-frag LDS bank = (4*row+col)%32, conflict-free.
template <bool DUAL>
__global__ void __launch_bounds__(256) k_gemm_tc(
    const float* __restrict__ A, const float* __restrict__ A2,
    const float* __restrict__ W0g, const float* __restrict__ W1g,
    const float* __restrict__ bias, float* __restrict__ C, int n, int relu)
{
    extern __shared__ uint32_t sm[];
    uint32_t* sW0 = sm;
    uint32_t* sW1 = DUAL ? (sm + 16384) : sm;
    uint32_t* sA  = sm + (DUAL ? 32768 : 16384);
    uint32_t* sA2 = DUAL ? (sA + 8448) : sA;

    int tid = threadIdx.x;
    int row0 = blockIdx.x * 64;

    // pack W into fragment order: [kstep(16)][ntile(16)][lane(32)][half(2)]
    for (int idx = tid; idx < 16384; idx += 256) {
        int k = idx >> 7, nn2 = idx & 127;
        int kstep = k >> 3, kin = k & 7, ntile = nn2 >> 3, nin = nn2 & 7;
        int lane = (nin << 2) | (kin & 3);
        int dest = (((kstep << 4) + ntile) << 6) + (lane << 1) + (kin >> 2);
        sW0[dest] = f2tf(__ldg(&W0g[idx]));
        if (DUAL) sW1[dest] = f2tf(__ldg(&W1g[idx]));
    }
    // stage A (tf32 bits), pad stride 132
    for (int idx = tid; idx < 8192; idx += 256) {
        int r = idx >> 7, c = idx & 127;
        int gr = row0 + r;
        sA[r * 132 + c] = (gr < n) ? f2tf(A[(size_t)gr * HD + c]) : 0u;
        if (DUAL) sA2[r * 132 + c] = (gr < n) ? f2tf(A2[(size_t)gr * HD + c]) : 0u;
    }
    __syncthreads();

    int wid = tid >> 5, lane = tid & 31;
    int tg = lane & 3, gid = lane >> 2;
    int nt0 = wid * 2;

    float acc[4][8];
#pragma unroll
    for (int s = 0; s < 4; s++)
#pragma unroll
        for (int j = 0; j < 8; j++) acc[s][j] = 0.f;

#pragma unroll 4
    for (int ks = 0; ks < 16; ks++) {
        const uint2* pB = reinterpret_cast<const uint2*>(sW0) + ((ks * 16 + nt0) * 32 + lane);
        uint2 b0 = pB[0];
        uint2 b1 = pB[32];
        uint2 d0, d1;
        if (DUAL) {
            const uint2* pB2 = reinterpret_cast<const uint2*>(sW1) + ((ks * 16 + nt0) * 32 + lane);
            d0 = pB2[0];
            d1 = pB2[32];
        }
        int ca = ks * 8 + tg;
#pragma unroll
        for (int s = 0; s < 4; s++) {
            int rb = (s * 16 + gid) * 132;
            uint32_t a0 = sA[rb + ca];
            uint32_t a1 = sA[rb + 8 * 132 + ca];
            uint32_t a2 = sA[rb + ca + 4];
            uint32_t a3 = sA[rb + 8 * 132 + ca + 4];
            MMA8(acc[s], a0, a1, a2, a3, b0.x, b0.y);
            MMA8(acc[s] + 4, a0, a1, a2, a3, b1.x, b1.y);
            if (DUAL) {
                uint32_t e0 = sA2[rb + ca];
                uint32_t e1 = sA2[rb + 8 * 132 + ca];
                uint32_t e2 = sA2[rb + ca + 4];
                uint32_t e3 = sA2[rb + 8 * 132 + ca + 4];
                MMA8(acc[s], e0, e1, e2, e3, d0.x, d0.y);
                MMA8(acc[s] + 4, e0, e1, e2, e3, d1.x, d1.y);
            }
        }
    }

    // epilogue
    int cbase = wid * 16;
    float bb[4] = {0.f, 0.f, 0.f, 0.f};
    if (bias) {
        bb[0] = __ldg(&bias[cbase + 2 * tg]);
        bb[1] = __ldg(&bias[cbase + 2 * tg + 1]);
        bb[2] = __ldg(&bias[cbase + 8 + 2 * tg]);
        bb[3] = __ldg(&bias[cbase + 8 + 2 * tg + 1]);
    }
#pragma unroll
    for (int s = 0; s < 4; s++) {
#pragma unroll
        for (int t = 0; t < 2; t++) {
            int col = cbase + t * 8 + 2 * tg;
            int r = row0 + s * 16 + gid;
            float v0 = acc[s][t * 4 + 0] + bb[t * 2 + 0];
            float v1 = acc[s][t * 4 + 1] + bb[t * 2 + 1];
            float v2 = acc[s][t * 4 + 2] + bb[t * 2 + 0];
            float v3 = acc[s][t * 4 + 3] + bb[t * 2 + 1];
            if (relu) {
                v0 = fmaxf(v0, 0.f); v1 = fmaxf(v1, 0.f);
                v2 = fmaxf(v2, 0.f); v3 = fmaxf(v3, 0.f);
            }
            if (r < n)
                *reinterpret_cast<float2*>(&C[(size_t)r * HD + col]) = make_float2(v0, v1);
            if (r + 8 < n)
                *reinterpret_cast<float2*>(&C[(size_t)(r + 8) * HD + col]) = make_float2(v2, v3);
        }
    }
}

// ---------------- node-head second stage: out = hidden . W2 + b2 (two heads) ----------------
__global__ void k_headreduce(const float* __restrict__ ha, const float* __restrict__ w2a,
                             const float* __restrict__ b2a,
                             const float* __restrict__ hb, const float* __restrict__ w2b,
                             const float* __restrict__ b2b,
                             float* __restrict__ pa, float* __restrict__ pb, int n)
{
    __shared__ float swa[128], swb[128];
    int tid = threadIdx.x;
    if (tid < 128) { swa[tid] = w2a[tid]; swb[tid] = w2b[tid]; }
    __syncthreads();
    int node = (blockIdx.x * blockDim.x + tid) >> 5;
    int lane = tid & 31;
    if (node >= n) return;
    float4 va = *reinterpret_cast<const float4*>(&ha[(size_t)node * HD + lane * 4]);
    float4 wa = *reinterpret_cast<const float4*>(&swa[lane * 4]);
    float sa = va.x * wa.x + va.y * wa.y + va.z * wa.z + va.w * wa.w;
    float4 vb = *reinterpret_cast<const float4*>(&hb[(size_t)node * HD + lane * 4]);
    float4 wb = *reinterpret_cast<const float4*>(&swb[lane * 4]);
    float sb = vb.x * wb.x + vb.y * wb.y + vb.z * wb.z + vb.w * wb.w;
#pragma unroll
    for (int off = 16; off; off >>= 1) {
        sa += __shfl_xor_sync(0xffffffffu, sa, off);
        sb += __shfl_xor_sync(0xffffffffu, sb, off);
    }
    if (lane == 0) {
        pa[node] = sa + __ldg(&b2a[0]);
        pb[node] = sb + __ldg(&b2b[0]);
    }
}

// ---------------- edge heads: one warp per edge, gather A[src]+B[dst]+static part ----------------
__global__ void k_edge(const int* __restrict__ ei,
                       const float* __restrict__ estat, const float* __restrict__ qobs,
                       const int* __restrict__ qmask,
                       const float* __restrict__ erW1, const float* __restrict__ erb1,
                       const float* __restrict__ erW2, const float* __restrict__ erb2,
                       const float* __restrict__ eaW1, const float* __restrict__ eab1,
                       const float* __restrict__ eaW2, const float* __restrict__ eab2,
                       float* __restrict__ qhat, float* __restrict__ elog, int ne)
{
    __shared__ float sE[2][8 * HD];  // per head: rows 0-5 = W1[256+r], 6 = b1, 7 = W2
    int tid = threadIdx.x;
    for (int idx = tid; idx < 2 * 8 * HD; idx += blockDim.x) {
        int h = idx / (8 * HD);
        int rem = idx - h * 8 * HD;
        int r = rem >> 7, c = rem & 127;
        const float* W1 = h ? eaW1 : erW1;
        const float* b1 = h ? eab1 : erb1;
        const float* W2 = h ? eaW2 : erW2;
        float v;
        if (r < 6) v = W1[(256 + r) * HD + c];
        else if (r == 6) v = b1[c];
        else v = W2[c];
        sE[h][rem] = v;
    }
    __syncthreads();

    int w = (blockIdx.x * blockDim.x + tid) >> 5;
    int lane = tid & 31;
    if (w >= ne) return;
    int s = ei[w], d = ei[ne + w];
    float e0 = estat[w * 4 + 0], e1 = estat[w * 4 + 1];
    float e2 = estat[w * 4 + 2], e3 = estat[w * 4 + 3];
    float qo = qobs[w], qm = (float)qmask[w];
    int c = lane * 4;

    {
        const float* S = sE[0];
        float4 a = *reinterpret_cast<const float4*>(&g_x[(size_t)s * HD + c]);
        float4 b = *reinterpret_cast<const float4*>(&g_agg[(size_t)d * HD + c]);
        float av[4] = {a.x, a.y, a.z, a.w};
        float bv[4] = {b.x, b.y, b.z, b.w};
        float acc = 0.f;
#pragma unroll
        for (int t = 0; t < 4; t++) {
            int cc = c + t;
            float hv = av[t] + bv[t] + e0 * S[cc] + e1 * S[HD + cc] + e2 * S[2 * HD + cc]
                     + e3 * S[3 * HD + cc] + qo * S[4 * HD + cc] + qm * S[5 * HD + cc]
                     + S[6 * HD + cc];
            hv = fmaxf(hv, 0.f);
            acc += hv * S[7 * HD + cc];
        }
#pragma unroll
        for (int off = 16; off; off >>= 1) acc += __shfl_xor_sync(0xffffffffu, acc, off);
        if (lane == 0) qhat[w] = acc + __ldg(&erb2[0]);
    }
    {
        const float* S = sE[1];
        float4 a = *reinterpret_cast<const float4*>(&g_p1[(size_t)s * HD + c]);
        float4 b = *reinterpret_cast<const float4*>(&g_p2[(size_t)d * HD + c]);
        float av[4] = {a.x, a.y, a.z, a.w};
        float bv[4] = {b.x, b.y, b.z, b.w};
        float acc = 0.f;
#pragma unroll
        for (int t = 0; t < 4; t++) {
            int cc = c + t;
            float hv = av[t] + bv[t] + e0 * S[cc] + e1 * S[HD + cc] + e2 * S[2 * HD + cc]
                     + e3 * S[3 * HD + cc] + qo * S[4 * HD + cc] + qm * S[5 * HD + cc]
                     + S[6 * HD + cc];
            hv = fmaxf(hv, 0.f);
            acc += hv * S[7 * HD + cc];
        }
#pragma unroll
        for (int off = 16; off; off >>= 1) acc += __shfl_xor_sync(0xffffffffu, acc, off);
        if (lane == 0) elog[w] = acc + __ldg(&eab2[0]);
    }
}

// ---------------- launch ----------------
extern "C" void kernel_launch(void* const* d_in, const int* in_sizes, int n_in,
                              void* d_out, int out_size)
{
    const int*   ei           = (const int*)d_in[0];   // edge_index is int32 (jax x64 disabled)
    const float* node_static  = (const float*)d_in[1];
    const float* edge_static  = (const float*)d_in[2];
    const float* p_obs        = (const float*)d_in[3];
    const float* q_obs        = (const float*)d_in[4];
    const int*   p_mask       = (const int*)d_in[5];
    const int*   q_mask       = (const int*)d_in[6];
    const float* W_enc        = (const float*)d_in[7];
    const float* b_enc        = (const float*)d_in[8];
    const float* W_self       = (const float*)d_in[9];
    const float* W_neigh      = (const float*)d_in[10];
    const float* b_gnn        = (const float*)d_in[11];
    const float* nrW1 = (const float*)d_in[12]; const float* nrb1 = (const float*)d_in[13];
    const float* nrW2 = (const float*)d_in[14]; const float* nrb2 = (const float*)d_in[15];
    const float* naW1 = (const float*)d_in[16]; const float* nab1 = (const float*)d_in[17];
    const float* naW2 = (const float*)d_in[18]; const float* nab2 = (const float*)d_in[19];
    const float* erW1 = (const float*)d_in[20]; const float* erb1 = (const float*)d_in[21];
    const float* erW2 = (const float*)d_in[22]; const float* erb2 = (const float*)d_in[23];
    const float* eaW1 = (const float*)d_in[24]; const float* eab1 = (const float*)d_in[25];
    const float* eaW2 = (const float*)d_in[26]; const float* eab2 = (const float*)d_in[27];

    int n  = in_sizes[3];  // N (p_obs)
    int ne = in_sizes[4];  // E (q_obs)

    float* out   = (float*)d_out;
    float* p_hat = out;
    float* q_hat = out + n;
    float* nlog  = out + n + ne;
    float* elog  = out + 2 * n + ne;

    float *gx, *gy, *gagg, *gp1, *gp2;
    cudaGetSymbolAddress((void**)&gx,   g_x);
    cudaGetSymbolAddress((void**)&gy,   g_y);
    cudaGetSymbolAddress((void**)&gagg, g_agg);
    cudaGetSymbolAddress((void**)&gp1,  g_p1);
    cudaGetSymbolAddress((void**)&gp2,  g_p2);

    const int SM_DUAL   = (16384 * 2 + 8448 * 2) * 4;  // 198656 B
    const int SM_SINGLE = (16384 + 8448) * 4;          //  99328 B
    cudaFuncSetAttribute(k_gemm_tc<true>,  cudaFuncAttributeMaxDynamicSharedMemorySize, SM_DUAL);
    cudaFuncSetAttribute(k_gemm_tc<false>, cudaFuncAttributeMaxDynamicSharedMemorySize, SM_SINGLE);

    k_encoder<<<(n * HD + 255) / 256, 256>>>(node_static, p_obs, p_mask, W_enc, b_enc, gx, n);
    k_zero_deg<<<(n + 255) / 256, 256>>>(n);
    k_deg<<<(ne + 255) / 256, 256>>>(ei, ne);
    int nb = (n + 1023) / 1024;
    k_scan_local<<<nb, 1024>>>(n);
    k_scan_bsum<<<1, 32>>>(nb);
    k_scan_final<<<(n + 255) / 256, 256>>>(n);
    k_fill<<<(ne + 255) / 256, 256>>>(ei, ne);

    int gblocks = (n + 63) / 64;
    const float* xin = gx;
    float* xout = gy;
    for (int l = 0; l < 3; l++) {
        k_agg<<<(n * 32 + 255) / 256, 256>>>(xin, gagg, n);
        k_gemm_tc<true><<<gblocks, 256, SM_DUAL>>>(xin, gagg,
                                                   W_self + l * HD * HD, W_neigh + l * HD * HD,
                                                   b_gnn + l * HD, xout, n, (l < 2) ? 1 : 0);
        const float* t = xin;
        xin = xout;
        xout = (float*)t;
    }
    const float* xf = xin;  // final node embeddings (g_y)

    // node heads: hidden = relu(xf@W1+b1) into g_x / g_agg, then warp-reduce with W2
    k_gemm_tc<false><<<gblocks, 256, SM_SINGLE>>>(xf, nullptr, nrW1, nullptr, nrb1, gx,  n, 1);
    k_gemm_tc<false><<<gblocks, 256, SM_SINGLE>>>(xf, nullptr, naW1, nullptr, nab1, gagg, n, 1);
    k_headreduce<<<(n * 32 + 255) / 256, 256>>>(gx, nrW2, nrb2, gagg, naW2, nab2, p_hat, nlog, n);

    // edge-head per-node precompute: er -> (g_x, g_agg), ea -> (g_p1, g_p2)
    k_gemm_tc<false><<<gblocks, 256, SM_SINGLE>>>(xf, nullptr, erW1,            nullptr, nullptr, gx,   n, 0);
    k_gemm_tc<false><<<gblocks, 256, SM_SINGLE>>>(xf, nullptr, erW1 + HD * HD,  nullptr, nullptr, gagg, n, 0);
    k_gemm_tc<false><<<gblocks, 256, SM_SINGLE>>>(xf, nullptr, eaW1,            nullptr, nullptr, gp1,  n, 0);
    k_gemm_tc<false><<<gblocks, 256, SM_SINGLE>>>(xf, nullptr, eaW1 + HD * HD,  nullptr, nullptr, gp2,  n, 0);

    k_edge<<<(ne * 32 + 255) / 256, 256>>>(ei, edge_static, q_obs, q_mask,
                                           erW1, erb1, erW2, erb2,
                                           eaW1, eab1, eaW2, eab2,
                                           q_hat, elog, ne);
}

// round 9
// speedup vs baseline: 3.1435x; 1.5359x over previous
#include <cuda_runtime.h>
#include <cstdint>

#define NN 100000
#define NE 600000
#define HD 128

// ---------------- scratch (static device memory; no allocs) ----------------
static __device__ float g_x  [NN * HD];
static __device__ float g_y  [NN * HD];
static __device__ float g_agg[NN * HD];
static __device__ float g_pairA[NN * 256];   // [node][0:128)=er A-part, [128:256)=ea A-part
static __device__ float g_pairB[NN * 256];   // [node][0:128)=er B-part, [128:256)=ea B-part
static __device__ int   g_deg[NN];
static __device__ int   g_rowptr[NN + 1];
static __device__ int   g_cursor[NN];
static __device__ int   g_col[2 * NE];
static __device__ float g_invdeg[NN];
static __device__ int   g_tmp[NN];
static __device__ int   g_bsum[128];
static __device__ uint32_t g_pw[12 * 16384]; // packed tf32 weights, fragment order

// ---------------- tf32 helpers ----------------
__device__ __forceinline__ uint32_t f2tf(float f)
{
    uint32_t r;
    asm("cvt.rna.tf32.f32 %0, %1;" : "=r"(r) : "f"(f));
    return r;
}

#define MMA8(c, a0, a1, a2, a3, b0, b1)                                     \
    asm volatile("mma.sync.aligned.m16n8k8.row.col.f32.tf32.tf32.f32 "      \
                 "{%0,%1,%2,%3},{%4,%5,%6,%7},{%8,%9},{%0,%1,%2,%3};"       \
                 : "+f"((c)[0]), "+f"((c)[1]), "+f"((c)[2]), "+f"((c)[3])   \
                 : "r"(a0), "r"(a1), "r"(a2), "r"(a3), "r"(b0), "r"(b1))

// ---------------- weight pre-pack: 12 matrices of 128x128 into fragment order ----------------
// frag layout: [kstep(16)][ntile(16)][lane(32)][half(2)] of uint32 (tf32 bits)
struct PackSrc { const float* s[12]; };

__global__ void k_pack(PackSrc ps)
{
    int idx = blockIdx.x * 256 + threadIdx.x;
    if (idx >= 12 * 16384) return;
    int m = idx >> 14, e = idx & 16383;
    int k = e >> 7, nn2 = e & 127;
    int kstep = k >> 3, kin = k & 7, ntile = nn2 >> 3, nin = nn2 & 7;
    int lane = (nin << 2) | (kin & 3);
    int dest = (((kstep << 4) + ntile) << 6) + (lane << 1) + (kin >> 2);
    g_pw[m * 16384 + dest] = f2tf(__ldg(&ps.s[m][e]));
}

// ---------------- encoder: x = node_feats(8) @ W_enc + b_enc ----------------
__global__ void k_encoder(const float* __restrict__ ns, const float* __restrict__ pobs,
                          const int* __restrict__ pmask, const float* __restrict__ Wenc,
                          const float* __restrict__ benc, float* __restrict__ x, int n)
{
    __shared__ float sW[8 * HD];
    __shared__ float sb[HD];
    for (int i = threadIdx.x; i < 8 * HD; i += blockDim.x) sW[i] = Wenc[i];
    for (int i = threadIdx.x; i < HD; i += blockDim.x) sb[i] = benc[i];
    __syncthreads();
    int idx = blockIdx.x * blockDim.x + threadIdx.x;
    if (idx >= n * HD) return;
    int node = idx >> 7, h = idx & 127;
    float f0 = ns[node * 6 + 0], f1 = ns[node * 6 + 1], f2 = ns[node * 6 + 2];
    float f3 = ns[node * 6 + 3], f4 = ns[node * 6 + 4], f5 = ns[node * 6 + 5];
    float f6 = pobs[node];
    float f7 = (float)pmask[node];
    float o = sb[h];
    o += f0 * sW[0 * HD + h] + f1 * sW[1 * HD + h] + f2 * sW[2 * HD + h] + f3 * sW[3 * HD + h];
    o += f4 * sW[4 * HD + h] + f5 * sW[5 * HD + h] + f6 * sW[6 * HD + h] + f7 * sW[7 * HD + h];
    x[idx] = o;
}

// ---------------- CSR build ----------------
__global__ void k_zero_deg(int n)
{
    int i = blockIdx.x * blockDim.x + threadIdx.x;
    if (i < n) g_deg[i] = 0;
}

__global__ void k_deg(const int* __restrict__ ei, int ne)
{
    int e = blockIdx.x * blockDim.x + threadIdx.x;
    if (e >= ne) return;
    int s = ei[e], d = ei[ne + e];
    atomicAdd(&g_deg[s], 1);
    atomicAdd(&g_deg[d], 1);
}

__global__ void k_scan_local(int n)
{
    __shared__ int sh[1024];
    int t = threadIdx.x;
    int i = blockIdx.x * 1024 + t;
    int v = (i < n) ? g_deg[i] : 0;
    sh[t] = v;
    __syncthreads();
    for (int off = 1; off < 1024; off <<= 1) {
        int tv = (t >= off) ? sh[t - off] : 0;
        __syncthreads();
        sh[t] += tv;
        __syncthreads();
    }
    if (i < n) g_tmp[i] = sh[t];
    if (t == 1023) g_bsum[blockIdx.x] = sh[1023];
}

__global__ void k_scan_bsum(int nb)
{
    if (threadIdx.x == 0) {
        int acc = 0;
        for (int b = 0; b < nb; b++) { int tv = g_bsum[b]; g_bsum[b] = acc; acc += tv; }
    }
}

__global__ void k_scan_final(int n)
{
    int i = blockIdx.x * blockDim.x + threadIdx.x;
    if (i >= n) return;
    int incl = g_tmp[i] + g_bsum[i >> 10];
    g_rowptr[i + 1] = incl;
    int d = g_deg[i];
    g_cursor[i] = incl - d;
    g_invdeg[i] = 1.0f / (float)(d > 0 ? d : 1);
    if (i == 0) g_rowptr[0] = 0;
}

__global__ void k_fill(const int* __restrict__ ei, int ne)
{
    int e = blockIdx.x * blockDim.x + threadIdx.x;
    if (e >= ne) return;
    int s = ei[e], d = ei[ne + e];
    int p = atomicAdd(&g_cursor[d], 1);
    g_col[p] = s;
    int q = atomicAdd(&g_cursor[s], 1);
    g_col[q] = d;
}

// ---------------- mean aggregation: one warp per node, x4 unrolled (MLP=4) ----------------
__global__ void k_agg(const float* __restrict__ x, float* __restrict__ agg, int n)
{
    int w = (blockIdx.x * blockDim.x + threadIdx.x) >> 5;
    int lane = threadIdx.x & 31;
    if (w >= n) return;
    int beg = g_rowptr[w], end = g_rowptr[w + 1];
    float4 acc = make_float4(0.f, 0.f, 0.f, 0.f);
    int i = beg;
    int c = lane * 4;
    for (; i + 4 <= end; i += 4) {
        int n0 = g_col[i], n1 = g_col[i + 1], n2 = g_col[i + 2], n3 = g_col[i + 3];
        float4 v0 = *reinterpret_cast<const float4*>(&x[(size_t)n0 * HD + c]);
        float4 v1 = *reinterpret_cast<const float4*>(&x[(size_t)n1 * HD + c]);
        float4 v2 = *reinterpret_cast<const float4*>(&x[(size_t)n2 * HD + c]);
        float4 v3 = *reinterpret_cast<const float4*>(&x[(size_t)n3 * HD + c]);
        acc.x += v0.x + v1.x + v2.x + v3.x;
        acc.y += v0.y + v1.y + v2.y + v3.y;
        acc.z += v0.z + v1.z + v2.z + v3.z;
        acc.w += v0.w + v1.w + v2.w + v3.w;
    }
    for (; i < end; i++) {
        int nb = g_col[i];
        float4 v = *reinterpret_cast<const float4*>(&x[(size_t)nb * HD + c]);
        acc.x += v.x; acc.y += v.y; acc.z += v.z; acc.w += v.w;
    }
    float sc = g_invdeg[w];
    acc.x *= sc; acc.y *= sc; acc.z *= sc; acc.w *= sc;
    *reinterpret_cast<float4*>(&agg[(size_t)w * HD + c]) = acc;
}

// ---------------- GEMM (dual-A): C = op(A@W0 + A2@W1 + bias), packed weights from global ----------------
// Block 256 thr / 8 warps, tile 64x128, K=128. Warp w: cols [w*16, w*16+16).
// A staged in smem stride 132 (conflict-free frag LDS). B frags LDG'd from L1-resident packed buffer.
__global__ void __launch_bounds__(256) k_gemm_dualA(
    const float* __restrict__ A, const float* __restrict__ A2,
    const uint32_t* __restrict__ pW0, const uint32_t* __restrict__ pW1,
    const float* __restrict__ bias, float* __restrict__ C, int n, int relu)
{
    extern __shared__ uint32_t sm[];
    uint32_t* sA  = sm;
    uint32_t* sA2 = sm + 8448;

    int tid = threadIdx.x;
    int row0 = blockIdx.x * 64;
    for (int idx = tid; idx < 8192; idx += 256) {
        int r = idx >> 7, cc = idx & 127;
        int gr = row0 + r;
        bool ok = gr < n;
        sA [r * 132 + cc] = ok ? f2tf(A [(size_t)gr * HD + cc]) : 0u;
        sA2[r * 132 + cc] = ok ? f2tf(A2[(size_t)gr * HD + cc]) : 0u;
    }
    __syncthreads();

    int wid = tid >> 5, lane = tid & 31;
    int tg = lane & 3, gid = lane >> 2;
    int nt0 = wid * 2;

    float acc[4][8];
#pragma unroll
    for (int s = 0; s < 4; s++)
#pragma unroll
        for (int j = 0; j < 8; j++) acc[s][j] = 0.f;

    const uint2* B0 = reinterpret_cast<const uint2*>(pW0) + (nt0 * 32 + lane);
    const uint2* B1 = reinterpret_cast<const uint2*>(pW1) + (nt0 * 32 + lane);

#pragma unroll 4
    for (int ks = 0; ks < 16; ks++) {
        uint2 b0 = __ldg(B0 + ks * 512);
        uint2 b1 = __ldg(B0 + ks * 512 + 32);
        uint2 d0 = __ldg(B1 + ks * 512);
        uint2 d1 = __ldg(B1 + ks * 512 + 32);
        int ca = ks * 8 + tg;
#pragma unroll
        for (int s = 0; s < 4; s++) {
            int rb = (s * 16 + gid) * 132;
            uint32_t a0 = sA[rb + ca];
            uint32_t a1 = sA[rb + 8 * 132 + ca];
            uint32_t a2 = sA[rb + ca + 4];
            uint32_t a3 = sA[rb + 8 * 132 + ca + 4];
            MMA8(acc[s], a0, a1, a2, a3, b0.x, b0.y);
            MMA8(acc[s] + 4, a0, a1, a2, a3, b1.x, b1.y);
            uint32_t e0 = sA2[rb + ca];
            uint32_t e1 = sA2[rb + 8 * 132 + ca];
            uint32_t e2 = sA2[rb + ca + 4];
            uint32_t e3 = sA2[rb + 8 * 132 + ca + 4];
            MMA8(acc[s], e0, e1, e2, e3, d0.x, d0.y);
            MMA8(acc[s] + 4, e0, e1, e2, e3, d1.x, d1.y);
        }
    }

    int cbase = wid * 16;
    float bb[4];
    bb[0] = __ldg(&bias[cbase + 2 * tg]);
    bb[1] = __ldg(&bias[cbase + 2 * tg + 1]);
    bb[2] = __ldg(&bias[cbase + 8 + 2 * tg]);
    bb[3] = __ldg(&bias[cbase + 8 + 2 * tg + 1]);
#pragma unroll
    for (int s = 0; s < 4; s++) {
#pragma unroll
        for (int t = 0; t < 2; t++) {
            int col = cbase + t * 8 + 2 * tg;
            int r = row0 + s * 16 + gid;
            float v0 = acc[s][t * 4 + 0] + bb[t * 2 + 0];
            float v1 = acc[s][t * 4 + 1] + bb[t * 2 + 1];
            float v2 = acc[s][t * 4 + 2] + bb[t * 2 + 0];
            float v3 = acc[s][t * 4 + 3] + bb[t * 2 + 1];
            if (relu) {
                v0 = fmaxf(v0, 0.f); v1 = fmaxf(v1, 0.f);
                v2 = fmaxf(v2, 0.f); v3 = fmaxf(v3, 0.f);
            }
            if (r < n)
                *reinterpret_cast<float2*>(&C[(size_t)r * HD + col]) = make_float2(v0, v1);
            if (r + 8 < n)
                *reinterpret_cast<float2*>(&C[(size_t)(r + 8) * HD + col]) = make_float2(v2, v3);
        }
    }
}

// ---------------- GEMM (dual-C): C0 = op(A@W0+b0), C1 = op(A@W1+b1), one A staging ----------------
__global__ void __launch_bounds__(256) k_gemm_dualC(
    const float* __restrict__ A,
    const uint32_t* __restrict__ pW0, const uint32_t* __restrict__ pW1,
    const float* __restrict__ bias0, const float* __restrict__ bias1,
    float* __restrict__ C0, float* __restrict__ C1, int cstride, int n, int relu)
{
    extern __shared__ uint32_t sm[];
    uint32_t* sA = sm;

    int tid = threadIdx.x;
    int row0 = blockIdx.x * 64;
    for (int idx = tid; idx < 8192; idx += 256) {
        int r = idx >> 7, cc = idx & 127;
        int gr = row0 + r;
        sA[r * 132 + cc] = (gr < n) ? f2tf(A[(size_t)gr * HD + cc]) : 0u;
    }
    __syncthreads();

    int wid = tid >> 5, lane = tid & 31;
    int tg = lane & 3, gid = lane >> 2;
    int nt0 = wid * 2;

    float acc0[4][8], acc1[4][8];
#pragma unroll
    for (int s = 0; s < 4; s++)
#pragma unroll
        for (int j = 0; j < 8; j++) { acc0[s][j] = 0.f; acc1[s][j] = 0.f; }

    const uint2* B0 = reinterpret_cast<const uint2*>(pW0) + (nt0 * 32 + lane);
    const uint2* B1 = reinterpret_cast<const uint2*>(pW1) + (nt0 * 32 + lane);

#pragma unroll 4
    for (int ks = 0; ks < 16; ks++) {
        uint2 b0 = __ldg(B0 + ks * 512);
        uint2 b1 = __ldg(B0 + ks * 512 + 32);
        uint2 d0 = __ldg(B1 + ks * 512);
        uint2 d1 = __ldg(B1 + ks * 512 + 32);
        int ca = ks * 8 + tg;
#pragma unroll
        for (int s = 0; s < 4; s++) {
            int rb = (s * 16 + gid) * 132;
            uint32_t a0 = sA[rb + ca];
            uint32_t a1 = sA[rb + 8 * 132 + ca];
            uint32_t a2 = sA[rb + ca + 4];
            uint32_t a3 = sA[rb + 8 * 132 + ca + 4];
            MMA8(acc0[s], a0, a1, a2, a3, b0.x, b0.y);
            MMA8(acc0[s] + 4, a0, a1, a2, a3, b1.x, b1.y);
            MMA8(acc1[s], a0, a1, a2, a3, d0.x, d0.y);
            MMA8(acc1[s] + 4, a0, a1, a2, a3, d1.x, d1.y);
        }
    }

    int cbase = wid * 16;
    float bb0[4] = {0.f, 0.f, 0.f, 0.f}, bb1[4] = {0.f, 0.f, 0.f, 0.f};
    if (bias0) {
        bb0[0] = __ldg(&bias0[cbase + 2 * tg]);
        bb0[1] = __ldg(&bias0[cbase + 2 * tg + 1]);
        bb0[2] = __ldg(&bias0[cbase + 8 + 2 * tg]);
        bb0[3] = __ldg(&bias0[cbase + 8 + 2 * tg + 1]);
    }
    if (bias1) {
        bb1[0] = __ldg(&bias1[cbase + 2 * tg]);
        bb1[1] = __ldg(&bias1[cbase + 2 * tg + 1]);
        bb1[2] = __ldg(&bias1[cbase + 8 + 2 * tg]);
        bb1[3] = __ldg(&bias1[cbase + 8 + 2 * tg + 1]);
    }
#pragma unroll
    for (int s = 0; s < 4; s++) {
#pragma unroll
        for (int t = 0; t < 2; t++) {
            int col = cbase + t * 8 + 2 * tg;
            int r = row0 + s * 16 + gid;
            float u0 = acc0[s][t * 4 + 0] + bb0[t * 2 + 0];
            float u1 = acc0[s][t * 4 + 1] + bb0[t * 2 + 1];
            float u2 = acc0[s][t * 4 + 2] + bb0[t * 2 + 0];
            float u3 = acc0[s][t * 4 + 3] + bb0[t * 2 + 1];
            float v0 = acc1[s][t * 4 + 0] + bb1[t * 2 + 0];
            float v1 = acc1[s][t * 4 + 1] + bb1[t * 2 + 1];
            float v2 = acc1[s][t * 4 + 2] + bb1[t * 2 + 0];
            float v3 = acc1[s][t * 4 + 3] + bb1[t * 2 + 1];
            if (relu) {
                u0 = fmaxf(u0, 0.f); u1 = fmaxf(u1, 0.f);
                u2 = fmaxf(u2, 0.f); u3 = fmaxf(u3, 0.f);
                v0 = fmaxf(v0, 0.f); v1 = fmaxf(v1, 0.f);
                v2 = fmaxf(v2, 0.f); v3 = fmaxf(v3, 0.f);
            }
            if (r < n) {
                *reinterpret_cast<float2*>(&C0[(size_t)r * cstride + col]) = make_float2(u0, u1);
                *reinterpret_cast<float2*>(&C1[(size_t)r * cstride + col]) = make_float2(v0, v1);
            }
            if (r + 8 < n) {
                *reinterpret_cast<float2*>(&C0[(size_t)(r + 8) * cstride + col]) = make_float2(u2, u3);
                *reinterpret_cast<float2*>(&C1[(size_t)(r + 8) * cstride + col]) = make_float2(v2, v3);
            }
        }
    }
}

// ---------------- node-head second stage: out = hidden . W2 + b2 (two heads) ----------------
__global__ void k_headreduce(const float* __restrict__ ha, const float* __restrict__ w2a,
                             const float* __restrict__ b2a,
                             const float* __restrict__ hb, const float* __restrict__ w2b,
                             const float* __restrict__ b2b,
                             float* __restrict__ pa, float* __restrict__ pb, int n)
{
    __shared__ float swa[128], swb[128];
    int tid = threadIdx.x;
    if (tid < 128) { swa[tid] = w2a[tid]; swb[tid] = w2b[tid]; }
    __syncthreads();
    int node = (blockIdx.x * blockDim.x + tid) >> 5;
    int lane = tid & 31;
    if (node >= n) return;
    float4 va = *reinterpret_cast<const float4*>(&ha[(size_t)node * HD + lane * 4]);
    float4 wa = *reinterpret_cast<const float4*>(&swa[lane * 4]);
    float sa = va.x * wa.x + va.y * wa.y + va.z * wa.z + va.w * wa.w;
    float4 vb = *reinterpret_cast<const float4*>(&hb[(size_t)node * HD + lane * 4]);
    float4 wb = *reinterpret_cast<const float4*>(&swb[lane * 4]);
    float sb = vb.x * wb.x + vb.y * wb.y + vb.z * wb.z + vb.w * wb.w;
#pragma unroll
    for (int off = 16; off; off >>= 1) {
        sa += __shfl_xor_sync(0xffffffffu, sa, off);
        sb += __shfl_xor_sync(0xffffffffu, sb, off);
    }
    if (lane == 0) {
        pa[node] = sa + __ldg(&b2a[0]);
        pb[node] = sb + __ldg(&b2b[0]);
    }
}

// ---------------- edge heads: one warp per edge, interleaved pair tables ----------------
__global__ void k_edge(const int* __restrict__ ei,
                       const float* __restrict__ estat, const float* __restrict__ qobs,
                       const int* __restrict__ qmask,
                       const float* __restrict__ erW1, const float* __restrict__ erb1,
                       const float* __restrict__ erW2, const float* __restrict__ erb2,
                       const float* __restrict__ eaW1, const float* __restrict__ eab1,
                       const float* __restrict__ eaW2, const float* __restrict__ eab2,
                       float* __restrict__ qhat, float* __restrict__ elog, int ne)
{
    __shared__ float sE[2][8 * HD];  // per head: rows 0-5 = W1[256+r], 6 = b1, 7 = W2
    int tid = threadIdx.x;
    for (int idx = tid; idx < 2 * 8 * HD; idx += blockDim.x) {
        int h = idx / (8 * HD);
        int rem = idx - h * 8 * HD;
        int r = rem >> 7, c = rem & 127;
        const float* W1 = h ? eaW1 : erW1;
        const float* b1 = h ? eab1 : erb1;
        const float* W2 = h ? eaW2 : erW2;
        float v;
        if (r < 6) v = W1[(256 + r) * HD + c];
        else if (r == 6) v = b1[c];
        else v = W2[c];
        sE[h][rem] = v;
    }
    __syncthreads();

    int w = (blockIdx.x * blockDim.x + tid) >> 5;
    int lane = tid & 31;
    if (w >= ne) return;
    int s = ei[w], d = ei[ne + w];
    float e0 = estat[w * 4 + 0], e1 = estat[w * 4 + 1];
    float e2 = estat[w * 4 + 2], e3 = estat[w * 4 + 3];
    float qo = qobs[w], qm = (float)qmask[w];
    int c = lane * 4;

    const float* srcA = &g_pairA[(size_t)s * 256];
    const float* dstB = &g_pairB[(size_t)d * 256];

    // head er: cols [0,128)
    {
        const float* S = sE[0];
        float4 a = *reinterpret_cast<const float4*>(&srcA[c]);
        float4 b = *reinterpret_cast<const float4*>(&dstB[c]);
        float av[4] = {a.x, a.y, a.z, a.w};
        float bv[4] = {b.x, b.y, b.z, b.w};
        float acc = 0.f;
#pragma unroll
        for (int t = 0; t < 4; t++) {
            int cc = c + t;
            float hv = av[t] + bv[t] + e0 * S[cc] + e1 * S[HD + cc] + e2 * S[2 * HD + cc]
                     + e3 * S[3 * HD + cc] + qo * S[4 * HD + cc] + qm * S[5 * HD + cc]
                     + S[6 * HD + cc];
            hv = fmaxf(hv, 0.f);
            acc += hv * S[7 * HD + cc];
        }
#pragma unroll
        for (int off = 16; off; off >>= 1) acc += __shfl_xor_sync(0xffffffffu, acc, off);
        if (lane == 0) qhat[w] = acc + __ldg(&erb2[0]);
    }
    // head ea: cols [128,256)
    {
        const float* S = sE[1];
        float4 a = *reinterpret_cast<const float4*>(&srcA[128 + c]);
        float4 b = *reinterpret_cast<const float4*>(&dstB[128 + c]);
        float av[4] = {a.x, a.y, a.z, a.w};
        float bv[4] = {b.x, b.y, b.z, b.w};
        float acc = 0.f;
#pragma unroll
        for (int t = 0; t < 4; t++) {
            int cc = c + t;
            float hv = av[t] + bv[t] + e0 * S[cc] + e1 * S[HD + cc] + e2 * S[2 * HD + cc]
                     + e3 * S[3 * HD + cc] + qo * S[4 * HD + cc] + qm * S[5 * HD + cc]
                     + S[6 * HD + cc];
            hv = fmaxf(hv, 0.f);
            acc += hv * S[7 * HD + cc];
        }
#pragma unroll
        for (int off = 16; off; off >>= 1) acc += __shfl_xor_sync(0xffffffffu, acc, off);
        if (lane == 0) elog[w] = acc + __ldg(&eab2[0]);
    }
}

// ---------------- launch ----------------
extern "C" void kernel_launch(void* const* d_in, const int* in_sizes, int n_in,
                              void* d_out, int out_size)
{
    const int*   ei           = (const int*)d_in[0];   // edge_index is int32 (jax x64 disabled)
    const float* node_static  = (const float*)d_in[1];
    const float* edge_static  = (const float*)d_in[2];
    const float* p_obs        = (const float*)d_in[3];
    const float* q_obs        = (const float*)d_in[4];
    const int*   p_mask       = (const int*)d_in[5];
    const int*   q_mask       = (const int*)d_in[6];
    const float* W_enc        = (const float*)d_in[7];
    const float* b_enc        = (const float*)d_in[8];
    const float* W_self       = (const float*)d_in[9];
    const float* W_neigh      = (const float*)d_in[10];
    const float* b_gnn        = (const float*)d_in[11];
    const float* nrW1 = (const float*)d_in[12]; const float* nrb1 = (const float*)d_in[13];
    const float* nrW2 = (const float*)d_in[14]; const float* nrb2 = (const float*)d_in[15];
    const float* naW1 = (const float*)d_in[16]; const float* nab1 = (const float*)d_in[17];
    const float* naW2 = (const float*)d_in[18]; const float* nab2 = (const float*)d_in[19];
    const float* erW1 = (const float*)d_in[20]; const float* erb1 = (const float*)d_in[21];
    const float* erW2 = (const float*)d_in[22]; const float* erb2 = (const float*)d_in[23];
    const float* eaW1 = (const float*)d_in[24]; const float* eab1 = (const float*)d_in[25];
    const float* eaW2 = (const float*)d_in[26]; const float* eab2 = (const float*)d_in[27];

    int n  = in_sizes[3];  // N (p_obs)
    int ne = in_sizes[4];  // E (q_obs)

    float* out   = (float*)d_out;
    float* p_hat = out;
    float* q_hat = out + n;
    float* nlog  = out + n + ne;
    float* elog  = out + 2 * n + ne;

    float *gx, *gy, *gagg, *gpa, *gpb;
    uint32_t* gpw;
    cudaGetSymbolAddress((void**)&gx,   g_x);
    cudaGetSymbolAddress((void**)&gy,   g_y);
    cudaGetSymbolAddress((void**)&gagg, g_agg);
    cudaGetSymbolAddress((void**)&gpa,  g_pairA);
    cudaGetSymbolAddress((void**)&gpb,  g_pairB);
    cudaGetSymbolAddress((void**)&gpw,  g_pw);

    const int SM_DUALA = 2 * 8448 * 4;  // 67584 B
    const int SM_ONEA  = 8448 * 4;      // 33792 B
    cudaFuncSetAttribute(k_gemm_dualA, cudaFuncAttributeMaxDynamicSharedMemorySize, SM_DUALA);
    cudaFuncSetAttribute(k_gemm_dualC, cudaFuncAttributeMaxDynamicSharedMemorySize, SM_ONEA);

    // pre-pack the 12 weight matrices: 0-2 Wself[l], 3-5 Wneigh[l], 6 nrW1, 7 naW1,
    // 8 erW1 top, 9 erW1 bot, 10 eaW1 top, 11 eaW1 bot
    PackSrc ps;
    ps.s[0] = W_self;                ps.s[1] = W_self + 16384;  ps.s[2] = W_self + 32768;
    ps.s[3] = W_neigh;               ps.s[4] = W_neigh + 16384; ps.s[5] = W_neigh + 32768;
    ps.s[6] = nrW1;                  ps.s[7] = naW1;
    ps.s[8] = erW1;                  ps.s[9] = erW1 + 16384;
    ps.s[10] = eaW1;                 ps.s[11] = eaW1 + 16384;
    k_pack<<<(12 * 16384 + 255) / 256, 256>>>(ps);

    k_encoder<<<(n * HD + 255) / 256, 256>>>(node_static, p_obs, p_mask, W_enc, b_enc, gx, n);
    k_zero_deg<<<(n + 255) / 256, 256>>>(n);
    k_deg<<<(ne + 255) / 256, 256>>>(ei, ne);
    int nb = (n + 1023) / 1024;
    k_scan_local<<<nb, 1024>>>(n);
    k_scan_bsum<<<1, 32>>>(nb);
    k_scan_final<<<(n + 255) / 256, 256>>>(n);
    k_fill<<<(ne + 255) / 256, 256>>>(ei, ne);

    int gblocks = (n + 63) / 64;
    const float* xin = gx;
    float* xout = gy;
    for (int l = 0; l < 3; l++) {
        k_agg<<<(n * 32 + 255) / 256, 256>>>(xin, gagg, n);
        k_gemm_dualA<<<gblocks, 256, SM_DUALA>>>(xin, gagg,
                                                 gpw + l * 16384, gpw + (3 + l) * 16384,
                                                 b_gnn + l * HD, xout, n, (l < 2) ? 1 : 0);
        const float* t = xin;
        xin = xout;
        xout = (float*)t;
    }
    const float* xf = xin;  // final node embeddings (g_y); g_x and g_agg now free

    // node heads: hidden = relu(xf@W1+b1) into g_x / g_agg, then warp-reduce with W2
    k_gemm_dualC<<<gblocks, 256, SM_ONEA>>>(xf, gpw + 6 * 16384, gpw + 7 * 16384,
                                            nrb1, nab1, gx, gagg, HD, n, 1);
    k_headreduce<<<(n * 32 + 255) / 256, 256>>>(gx, nrW2, nrb2, gagg, naW2, nab2, p_hat, nlog, n);

    // edge-head per-node precompute (interleaved): er -> cols [0,128), ea -> cols [128,256)
    k_gemm_dualC<<<gblocks, 256, SM_ONEA>>>(xf, gpw + 8 * 16384, gpw + 9 * 16384,
                                            nullptr, nullptr, gpa, gpb, 256, n, 0);
    k_gemm_dualC<<<gblocks, 256, SM_ONEA>>>(xf, gpw + 10 * 16384, gpw + 11 * 16384,
                                            nullptr, nullptr, gpa + 128, gpb + 128, 256, n, 0);

    k_edge<<<(ne * 32 + 255) / 256, 256>>>(ei, edge_static, q_obs, q_mask,
                                           erW1, erb1, erW2, erb2,
                                           eaW1, eab1, eaW2, eab2,
                                           q_hat, elog, ne);
}